// round 12
// baseline (speedup 1.0000x reference)
#include <cuda_runtime.h>
#include <cuda_bf16.h>

// Embedding gather: out[token, :] = table[ids[token], :]
// ids: [32*8192] int32, table: [256,256] f32, out: [32*8192, 256] f32.
//
// Converged structure: steady-state DRAM-write-roofline-bound (268 MB per
// replay period ≈ 6.5 TB/s sustained HBM writes ≈ 82% of spec; seven
// structural variants converged to 39.2-39.9 us kernel time). Each block
// owns one contiguous output chunk; each thread runs 4 independent
// gather->store chains with lane-contiguous float4 accesses (512 B / 4 L1
// lines per warp instruction). ids loads are warp-uniform broadcasts; the
// 256 KB table is L1/L2-resident. 32-bit indexing throughout. Default store
// policy (measured >= .cs). R12: 512-thread blocks (32 KB/block, 8192
// blocks) to trim block-tail overhead; otherwise identical to R11.

static constexpr int TOKENS       = 32 * 8192;           // 262144
static constexpr int EMBED        = 256;
static constexpr int VEC_PER_ROW  = EMBED / 4;           // 64 float4 per row
static constexpr int TOTAL_VEC4   = TOKENS * VEC_PER_ROW;// 16,777,216 (< 2^31)
static constexpr int ITEMS        = 4;                   // chains per thread
static constexpr int THREADS      = 512;

__global__ __launch_bounds__(THREADS)
void embed_gather_kernel(const int* __restrict__ ids,
                         const float4* __restrict__ table4,
                         float4* __restrict__ out4)
{
    // Block b owns float4 range [b*2048, (b+1)*2048), k steps by 512 (8 KB).
    const unsigned base = blockIdx.x * (unsigned)(ITEMS * THREADS) + threadIdx.x;

    unsigned g[ITEMS];
    int      tok[ITEMS];
    float4   v[ITEMS];

    // Batched index loads (warp-uniform -> single broadcast L1 hit each).
    #pragma unroll
    for (int k = 0; k < ITEMS; k++) {
        g[k]   = base + (unsigned)(k * THREADS);
        tok[k] = __ldg(&ids[g[k] >> 6]);
    }

    // Batched table loads (4 independent LDG.128; table resident in L1/L2).
    #pragma unroll
    for (int k = 0; k < ITEMS; k++) {
        v[k] = __ldg(&table4[(unsigned)tok[k] * (unsigned)VEC_PER_ROW + (g[k] & 63u)]);
    }

    // Default-policy stores: contiguous 8 KB per block per k-step.
    #pragma unroll
    for (int k = 0; k < ITEMS; k++) {
        out4[g[k]] = v[k];
    }
}

extern "C" void kernel_launch(void* const* d_in, const int* in_sizes, int n_in,
                              void* d_out, int out_size)
{
    const int*   ids   = (const int*)d_in[0];    // [32, 8192] int32
    const float* table = (const float*)d_in[1];  // [256, 256] f32
    float*       out   = (float*)d_out;          // [32, 8192, 256] f32

    const int blocks = TOTAL_VEC4 / (ITEMS * THREADS);   // 8192

    embed_gather_kernel<<<blocks, THREADS>>>(
        ids, (const float4*)table, (float4*)out);
}

// round 13
// speedup vs baseline: 1.0174x; 1.0174x over previous
#include <cuda_runtime.h>
#include <cuda_bf16.h>

// Embedding gather: out[token, :] = table[ids[token], :]
// ids: [32*8192] int32, table: [256,256] f32, out: [32*8192, 256] f32.
//
// FINAL. Steady-state DRAM-write-roofline-bound: 268 MB of output must
// drain to HBM every replay period (~6.4 TB/s sustained ≈ 80%+ of spec).
// Eight structural variants (MLP 4/8, reg budgets, scattered vs contiguous
// writes, .cs vs default policy, TMA bulk store, id-sorted store-only
// streaming, 256 vs 512 threads) all converged to 39.2-43.7 us kernel time;
// this configuration measured fastest (39.20 us, DRAM 67.6%, ALU 5.8%).
//
// Structure: 16384 blocks x 256 threads; each block owns one contiguous
// 16 KB output chunk; each thread runs 4 independent gather->store chains
// (k steps 4 KB) with lane-contiguous float4 accesses (512 B / 4 L1 lines
// per warp instruction). ids loads are warp-uniform broadcasts; the 256 KB
// table is L1/L2-resident. 32-bit indexing keeps the address chains to
// single IMADs. Default store policy (measured >= .cs evict-first).

static constexpr int TOKENS       = 32 * 8192;           // 262144
static constexpr int EMBED        = 256;
static constexpr int VEC_PER_ROW  = EMBED / 4;           // 64 float4 per row
static constexpr int TOTAL_VEC4   = TOKENS * VEC_PER_ROW;// 16,777,216 (< 2^31)
static constexpr int ITEMS        = 4;                   // chains per thread
static constexpr int THREADS      = 256;

__global__ __launch_bounds__(THREADS)
void embed_gather_kernel(const int* __restrict__ ids,
                         const float4* __restrict__ table4,
                         float4* __restrict__ out4)
{
    // Block b owns float4 range [b*1024, (b+1)*1024), k steps by 256 (4 KB).
    const unsigned base = blockIdx.x * (unsigned)(ITEMS * THREADS) + threadIdx.x;

    unsigned g[ITEMS];
    int      tok[ITEMS];
    float4   v[ITEMS];

    // Batched index loads (warp-uniform -> single broadcast L1 hit each).
    #pragma unroll
    for (int k = 0; k < ITEMS; k++) {
        g[k]   = base + (unsigned)(k * THREADS);
        tok[k] = __ldg(&ids[g[k] >> 6]);
    }

    // Batched table loads (4 independent LDG.128; table resident in L1/L2).
    #pragma unroll
    for (int k = 0; k < ITEMS; k++) {
        v[k] = __ldg(&table4[(unsigned)tok[k] * (unsigned)VEC_PER_ROW + (g[k] & 63u)]);
    }

    // Default-policy stores: contiguous 4 KB per block per k-step.
    #pragma unroll
    for (int k = 0; k < ITEMS; k++) {
        out4[g[k]] = v[k];
    }
}

extern "C" void kernel_launch(void* const* d_in, const int* in_sizes, int n_in,
                              void* d_out, int out_size)
{
    const int*   ids   = (const int*)d_in[0];    // [32, 8192] int32
    const float* table = (const float*)d_in[1];  // [256, 256] f32
    float*       out   = (float*)d_out;          // [32, 8192, 256] f32

    const int blocks = TOTAL_VEC4 / (ITEMS * THREADS);   // 16384

    embed_gather_kernel<<<blocks, THREADS>>>(
        ids, (const float4*)table, (float4*)out);
}